// round 9
// baseline (speedup 1.0000x reference)
#include <cuda_runtime.h>
#include <cuda_fp16.h>
#include <cstdint>

#define Nn     5000
#define TST    5024          // fp32 buffer node stride
#define TSTH   5056          // fp16 buffer node stride (79*64)
#define NF     33
#define NU     32
#define TENC   12
#define TDEC   12
#define BM     64
#define MT     79            // ceil(5000/64)
#define SPLITK 5
#define GGRID  (MT*SPLITK)   // 395
#define KT     79            // K tiles of 64
#define BK     64
#define NSTG   5
#define LDH    72            // fp16 smem row stride (64 + 8 pad)
#define ASH_W  (BM*LDH)      // 4608 halfs / stage
#define BSH_W  (40*LDH)      // 2880 halfs / stage
#define DSMEM  (NSTG*(ASH_W+BSH_W)*2)   // 74880 bytes
#define TXBYTES (BM*128 + NF*128)       // 12416 bytes per stage

// ---------------- persistent device state ----------------
__device__ __half gAh[25000000];               // fp16 copy of adj (50MB)
__device__ __align__(16) float g_X0T[NF*TST];
__device__ __align__(16) float g_X1T[NF*TST];
__device__ __align__(16) float g_X2T[NF*TST];
__device__ __align__(16) float g_C0T[NF*TST];
__device__ __align__(16) float g_C1T[NF*TST];
__device__ __align__(16) float g_C2T[NF*TST];
__device__ __align__(16) __half g_X0h[NF*TSTH];
__device__ __align__(16) __half g_X1h[NF*TSTH];
__device__ __align__(16) __half g_C0h[NF*TSTH];
__device__ __align__(16) __half g_C1h[NF*TSTH];
__device__ float g_hT[NU*TST];
__device__ float g_uT[NU*TST];
__device__ unsigned g_cnt0[MT];                // split-K completion counters
__device__ unsigned g_cnt2[MT];

// ---------------- helpers ----------------
__device__ __forceinline__ unsigned su32(const void* p) {
    return (unsigned)__cvta_generic_to_shared(p);
}
__device__ __forceinline__ void bulk_cp(unsigned dst, const void* src,
                                        unsigned bytes, unsigned mbar) {
    asm volatile("cp.async.bulk.shared::cluster.global.mbarrier::complete_tx::bytes "
                 "[%0], [%1], %2, [%3];"
                 :: "r"(dst), "l"(src), "r"(bytes), "r"(mbar) : "memory");
}
__device__ __forceinline__ void mbar_init(unsigned a, unsigned c) {
    asm volatile("mbarrier.init.shared.b64 [%0], %1;" :: "r"(a), "r"(c) : "memory");
}
__device__ __forceinline__ void mbar_expect(unsigned a, unsigned tx) {
    asm volatile("mbarrier.arrive.expect_tx.shared.b64 _, [%0], %1;"
                 :: "r"(a), "r"(tx) : "memory");
}
__device__ __forceinline__ void mbar_wait(unsigned a, unsigned ph) {
    asm volatile("{\n\t.reg .pred P;\n\t"
                 "W%=:\n\tmbarrier.try_wait.parity.acquire.cta.shared::cta.b64 P, [%0], %1, 0x989680;\n\t"
                 "@!P bra W%=;\n\t}" :: "r"(a), "r"(ph) : "memory");
}
__device__ __forceinline__ void mma_f16(float* c, unsigned a0, unsigned a1,
                                        unsigned a2, unsigned a3,
                                        unsigned b0, unsigned b1) {
    asm volatile("mma.sync.aligned.m16n8k16.row.col.f32.f16.f16.f32 "
                 "{%0,%1,%2,%3}, {%4,%5,%6,%7}, {%8,%9}, {%0,%1,%2,%3};"
                 : "+f"(c[0]), "+f"(c[1]), "+f"(c[2]), "+f"(c[3])
                 : "r"(a0), "r"(a1), "r"(a2), "r"(a3), "r"(b0), "r"(b1));
}

// ============================================================================
// fp16 mma GEMM: YT(f,r) += sum_k A(r,k) * Xh(f,k)
// 64 rows/CTA, N=40 (33 used), K-tiles of 64, split-K=5.
// cp.async.bulk loads (97 ops/tile), 5-stage mbarrier ring, depth-4 lookahead.
// sel 0/2: last split-K CTA per M-tile converts fp32 output -> fp16 shadow.
// ============================================================================
__global__ void __launch_bounds__(128, 3) gemm_mma(int sel)
{
    const __half* __restrict__ XH;
    float* __restrict__ YT;
    __half* __restrict__ DH = nullptr;
    unsigned* cnt = nullptr;
    switch (sel) {
        case 0:  XH = g_X0h; YT = g_X1T; DH = g_X1h; cnt = g_cnt0; break;
        case 1:  XH = g_X1h; YT = g_X2T; break;
        case 2:  XH = g_C0h; YT = g_C1T; DH = g_C1h; cnt = g_cnt2; break;
        default: XH = g_C1h; YT = g_C2T; break;
    }

    extern __shared__ __half smh[];
    __half* as = smh;                  // [5][64][72]
    __half* bs = smh + NSTG*ASH_W;     // [5][40][72]
    __shared__ __align__(8) unsigned long long mbar[NSTG];
    __shared__ int isLast;

    const int t    = threadIdx.x;
    const int w    = t >> 5, lane = t & 31;
    const int r4   = lane >> 2, c4 = lane & 3;
    const int rt   = blockIdx.x % MT;
    const int ck   = blockIdx.x / MT;
    const int row0 = rt * BM;
    const int tS   = (KT * ck)       / SPLITK;
    const int tE   = (KT * (ck + 1)) / SPLITK;
    const int nt   = tE - tS;

    if (t == 0) {
        #pragma unroll
        for (int s = 0; s < NSTG; ++s) mbar_init(su32(&mbar[s]), 1);
    }
    // zero B pad rows 33..39 in all stages
    for (int i = t; i < NSTG * 7 * BK; i += 128) {
        int s = i / (7 * BK), rem = i % (7 * BK);
        bs[s*BSH_W + (33 + rem / BK) * LDH + (rem % BK)] = __half(0.f);
    }
    asm volatile("fence.proxy.async.shared::cta;" ::: "memory");
    __syncthreads();

    const int arow = row0 + t < Nn ? row0 + t : Nn - 1;   // for t < 64
    const __half* aRowBase = gAh + (long)arow * Nn;

    auto load_tile = [&](int tile, int s) {
        const int k0 = tile * BK;
        const unsigned mb = su32(&mbar[s]);
        if (t == 0) mbar_expect(mb, TXBYTES);
        if (t < BM) {
            // A row t: 128 contiguous bytes (k clamped; tail garbage masked by B=0 / r<Nn)
            int gk = k0 + BK <= Nn ? k0 : Nn - BK;
            bulk_cp(su32(as + s*ASH_W + t*LDH), aRowBase + gk, 128, mb);
        } else if (t < BM + NF) {
            int row = t - BM;
            bulk_cp(su32(bs + s*BSH_W + row*LDH), XH + (long)row*TSTH + k0, 128, mb);
        }
    };

    float acc[5][4];
    #pragma unroll
    for (int ct = 0; ct < 5; ++ct)
        #pragma unroll
        for (int i = 0; i < 4; ++i) acc[ct][i] = 0.f;

    #pragma unroll
    for (int p = 0; p < 4; ++p)
        if (p < nt) load_tile(tS + p, p);

    for (int i = 0; i < nt; ++i) {
        __syncthreads();                       // all warps done with iter i-1
        if (i + 4 < nt) load_tile(tS + i + 4, (i + 4) % NSTG);
        mbar_wait(su32(&mbar[i % NSTG]), (unsigned)(i / NSTG) & 1);

        const int stage = i % NSTG;
        const __half* aB = as + stage*ASH_W + (w*16)*LDH;
        const __half* bB = bs + stage*BSH_W;
        #pragma unroll
        for (int ks = 0; ks < 4; ++ks) {
            const int kb = ks*16 + 2*c4;
            unsigned a0 = *(const unsigned*)(aB + (r4    )*LDH + kb    );
            unsigned a1 = *(const unsigned*)(aB + (r4 + 8)*LDH + kb    );
            unsigned a2 = *(const unsigned*)(aB + (r4    )*LDH + kb + 8);
            unsigned a3 = *(const unsigned*)(aB + (r4 + 8)*LDH + kb + 8);
            #pragma unroll
            for (int ct = 0; ct < 5; ++ct) {
                unsigned b0 = *(const unsigned*)(bB + (ct*8 + r4)*LDH + kb    );
                unsigned b1 = *(const unsigned*)(bB + (ct*8 + r4)*LDH + kb + 8);
                mma_f16(acc[ct], a0, a1, a2, a3, b0, b1);
            }
        }
    }

    const int rA = row0 + w*16 + r4;
    const int rB = rA + 8;
    #pragma unroll
    for (int ct = 0; ct < 5; ++ct) {
        const int col0 = ct*8 + 2*c4;
        const int col1 = col0 + 1;
        if (col0 < NF) {
            if (rA < Nn) atomicAdd(YT + (long)col0*TST + rA, acc[ct][0]);
            if (rB < Nn) atomicAdd(YT + (long)col0*TST + rB, acc[ct][2]);
        }
        if (col1 < NF) {
            if (rA < Nn) atomicAdd(YT + (long)col1*TST + rA, acc[ct][1]);
            if (rB < Nn) atomicAdd(YT + (long)col1*TST + rB, acc[ct][3]);
        }
    }

    // fused fp32 -> fp16 conversion by the last split-K CTA of this M-tile
    if (DH) {
        __threadfence();
        if (t == 0) isLast = (atomicAdd(&cnt[rt], 1u) == SPLITK - 1);
        __syncthreads();
        if (isLast) {
            __threadfence();
            for (int idx = t; idx < BM * NF; idx += 128) {
                int c = idx / BM, r = row0 + (idx % BM);
                if (r < Nn) DH[(long)c*TSTH + r] = __float2half_rn(YT[(long)c*TST + r]);
            }
            if (t == 0) cnt[rt] = 0;
        }
    }
}

// ============================================================================
// Prep / elementwise kernels
// ============================================================================
__global__ void conv_A(const float* __restrict__ A) {
    long i0 = (long)blockIdx.x * blockDim.x + threadIdx.x;
    long stride = (long)gridDim.x * blockDim.x;
    for (long i = i0; i < (long)Nn * Nn; i += stride) gAh[i] = __float2half_rn(A[i]);
}

__global__ void init_k() {
    int tid = blockIdx.x * blockDim.x + threadIdx.x;
    int nth = gridDim.x * blockDim.x;
    for (int j = tid; j < NF * TST; j += nth) {
        g_X0T[j] = 0.f; g_X1T[j] = 0.f; g_X2T[j] = 0.f;
        g_C0T[j] = 0.f; g_C1T[j] = 0.f; g_C2T[j] = 0.f;
    }
    for (int j = tid; j < NF * TSTH; j += nth) {
        g_X0h[j] = __half(0.f); g_X1h[j] = __half(0.f);
        g_C0h[j] = __half(0.f); g_C1h[j] = __half(0.f);
    }
    for (int j = tid; j < NU * TST; j += nth) { g_hT[j] = 0.f; g_uT[j] = 0.f; }
    for (int j = tid; j < MT; j += nth) { g_cnt0[j] = 0u; g_cnt2[j] = 0u; }
}

__global__ void build_enc(const float* __restrict__ inp, int tstep) {
    int tid = blockIdx.x * blockDim.x + threadIdx.x;
    int nth = gridDim.x * blockDim.x;
    for (int j = tid; j < NF * TST; j += nth) {
        int c = j / TST, n = j - c * TST;
        float v = 0.f;
        if (n < Nn) v = (c == 0) ? inp[n * TENC + tstep] : g_hT[(c - 1) * TST + n];
        g_X0T[j] = v;
        g_X0h[c * TSTH + n] = __float2half_rn(v);
        g_X1T[j] = 0.f; g_X2T[j] = 0.f;
    }
}

__global__ void build_dec0() {
    int tid = blockIdx.x * blockDim.x + threadIdx.x;
    int nth = gridDim.x * blockDim.x;
    for (int j = tid; j < NF * TST; j += nth) {
        int c = j / TST, n = j - c * TST;
        float v = 0.f;
        if (n < Nn && c > 0) v = g_hT[(c - 1) * TST + n];
        g_X0T[j] = v;
        g_X0h[c * TSTH + n] = __float2half_rn(v);
        g_X1T[j] = 0.f; g_X2T[j] = 0.f;
    }
}

__global__ void __launch_bounds__(256) gate_k(const float* __restrict__ W,
                                              const float* __restrict__ b) {
    __shared__ float sW[99 * 64];
    __shared__ float sx[99 * 32];
    const int t = threadIdx.x, lane = t & 31, w = t >> 5;
    const int rowb = blockIdx.x * 32;
    for (int j = t; j < 99 * 64; j += 256) sW[j] = W[j];
    for (int j = t; j < 99 * 32; j += 256) {
        int c = j >> 5, i = j & 31;
        const float* src = (c < 33) ? (g_X0T + c * TST)
                         : (c < 66) ? (g_X1T + (c - 33) * TST)
                                    : (g_X2T + (c - 66) * TST);
        sx[j] = src[rowb + i];
    }
    __syncthreads();

    float acc[8];
    #pragma unroll
    for (int cc = 0; cc < 8; ++cc) acc[cc] = b[8 * w + cc];
    for (int k = 0; k < 99; ++k) {
        float xv = sx[k * 32 + lane];
        const float4* wr = reinterpret_cast<const float4*>(sW + k * 64 + 8 * w);
        float4 w0 = wr[0], w1 = wr[1];
        acc[0] = fmaf(xv, w0.x, acc[0]); acc[1] = fmaf(xv, w0.y, acc[1]);
        acc[2] = fmaf(xv, w0.z, acc[2]); acc[3] = fmaf(xv, w0.w, acc[3]);
        acc[4] = fmaf(xv, w1.x, acc[4]); acc[5] = fmaf(xv, w1.y, acc[5]);
        acc[6] = fmaf(xv, w1.z, acc[6]); acc[7] = fmaf(xv, w1.w, acc[7]);
    }
    int row = rowb + lane;
    if (row < Nn) {
        #pragma unroll
        for (int cc = 0; cc < 8; ++cc) {
            int col = 8 * w + cc;
            float s = 1.f / (1.f + expf(-acc[cc]));
            if (col < 32) {
                float rh = s * g_hT[col * TST + row];
                g_C0T[(1 + col) * TST + row] = rh;
                g_C0h[(1 + col) * TSTH + row] = __float2half_rn(rh);
            } else {
                g_uT[(col - 32) * TST + row] = s;
            }
        }
        if (w == 0) {
            g_C0T[row] = g_X0T[row];
            g_C0h[row] = g_X0h[row];
        }
    }
    int tid = blockIdx.x * 256 + t, nth = gridDim.x * 256;
    for (int j = tid; j < NF * TST; j += nth) { g_C1T[j] = 0.f; g_C2T[j] = 0.f; }
}

__global__ void __launch_bounds__(256) cand_k(const float* __restrict__ W,
                                              const float* __restrict__ b) {
    __shared__ float sW[99 * 32];
    __shared__ float sx[99 * 32];
    const int t = threadIdx.x, lane = t & 31, w = t >> 5;
    const int rowb = blockIdx.x * 32;
    for (int j = t; j < 99 * 32; j += 256) sW[j] = W[j];
    for (int j = t; j < 99 * 32; j += 256) {
        int c = j >> 5, i = j & 31;
        const float* src = (c < 33) ? (g_C0T + c * TST)
                         : (c < 66) ? (g_C1T + (c - 33) * TST)
                                    : (g_C2T + (c - 66) * TST);
        sx[j] = src[rowb + i];
    }
    __syncthreads();

    float acc[4];
    #pragma unroll
    for (int cc = 0; cc < 4; ++cc) acc[cc] = b[4 * w + cc];
    for (int k = 0; k < 99; ++k) {
        float xv = sx[k * 32 + lane];
        float4 wv = *reinterpret_cast<const float4*>(sW + k * 32 + 4 * w);
        acc[0] = fmaf(xv, wv.x, acc[0]); acc[1] = fmaf(xv, wv.y, acc[1]);
        acc[2] = fmaf(xv, wv.z, acc[2]); acc[3] = fmaf(xv, wv.w, acc[3]);
    }
    int row = rowb + lane;
    if (row < Nn) {
        #pragma unroll
        for (int cc = 0; cc < 4; ++cc) {
            int col = 4 * w + cc;
            float c = tanhf(acc[cc]);
            float u = g_uT[col * TST + row];
            float h = g_hT[col * TST + row];
            g_hT[col * TST + row] = u * h + (1.f - u) * c;
        }
    }
}

__global__ void __launch_bounds__(256) dec_post(const float* __restrict__ Wp,
                                                const float* __restrict__ bp,
                                                float* __restrict__ out, int tstep) {
    int tid = blockIdx.x * 256 + threadIdx.x;
    int nth = gridDim.x * 256;
    for (int row = tid; row < Nn; row += nth) {
        float acc = bp[0];
        #pragma unroll
        for (int c = 0; c < 32; ++c) acc = fmaf(g_hT[c * TST + row], Wp[c], acc);
        out[row * TDEC + tstep] = acc;
        g_X0T[row] = acc;
        g_X0h[row] = __float2half_rn(acc);
    }
    for (int j = tid; j < NU * TST; j += nth) {
        int c = j / TST, n = j - c * TST;
        float h = g_hT[j];
        g_X0T[TST + j] = h;
        g_X0h[(1 + c) * TSTH + n] = __float2half_rn(h);
    }
    for (int j = tid; j < NF * TST; j += nth) { g_X1T[j] = 0.f; g_X2T[j] = 0.f; }
}

// ============================================================================
// Host launch sequence
// ============================================================================
extern "C" void kernel_launch(void* const* d_in, const int* in_sizes, int n_in,
                              void* d_out, int out_size) {
    const float* inputs = (const float*)d_in[0];
    const float* adj    = (const float*)d_in[2];
    const float* enc_Wg = (const float*)d_in[3];
    const float* enc_bg = (const float*)d_in[4];
    const float* enc_Wc = (const float*)d_in[5];
    const float* enc_bc = (const float*)d_in[6];
    const float* dec_Wg = (const float*)d_in[7];
    const float* dec_bg = (const float*)d_in[8];
    const float* dec_Wc = (const float*)d_in[9];
    const float* dec_bc = (const float*)d_in[10];
    const float* dec_Wp = (const float*)d_in[11];
    const float* dec_bp = (const float*)d_in[12];
    float* out = (float*)d_out;

    cudaFuncSetAttribute(gemm_mma, cudaFuncAttributeMaxDynamicSharedMemorySize, DSMEM);
    cudaFuncSetAttribute(gemm_mma, cudaFuncAttributePreferredSharedMemoryCarveout, 100);

    conv_A<<<1024, 256>>>(adj);
    init_k<<<256, 256>>>();

    for (int t = 0; t < TENC; ++t) {
        build_enc<<<256, 256>>>(inputs, t);
        gemm_mma<<<GGRID, 128, DSMEM>>>(0);
        gemm_mma<<<GGRID, 128, DSMEM>>>(1);
        gate_k<<<157, 256>>>(enc_Wg, enc_bg);
        gemm_mma<<<GGRID, 128, DSMEM>>>(2);
        gemm_mma<<<GGRID, 128, DSMEM>>>(3);
        cand_k<<<157, 256>>>(enc_Wc, enc_bc);
    }

    build_dec0<<<256, 256>>>();
    for (int t = 0; t < TDEC; ++t) {
        gemm_mma<<<GGRID, 128, DSMEM>>>(0);
        gemm_mma<<<GGRID, 128, DSMEM>>>(1);
        gate_k<<<157, 256>>>(dec_Wg, dec_bg);
        gemm_mma<<<GGRID, 128, DSMEM>>>(2);
        gemm_mma<<<GGRID, 128, DSMEM>>>(3);
        cand_k<<<157, 256>>>(dec_Wc, dec_bc);
        dec_post<<<157, 256>>>(dec_Wp, dec_bp, out, t);
    }
}

// round 10
// speedup vs baseline: 1.1342x; 1.1342x over previous
#include <cuda_runtime.h>
#include <cuda_fp16.h>
#include <cstdint>

#define Nn     5000
#define TST    5024          // fp32 buffer node stride
#define TSTH   5056          // fp16 buffer node stride (79*64)
#define NF     33
#define NU     32
#define TENC   12
#define TDEC   12
#define BM     64
#define MT     79            // ceil(5000/64)
#define SPLITK 5
#define GGRID  (MT*SPLITK)   // 395
#define KT     79            // K tiles of 64
#define BK     64
#define NSTG   5
#define LDH    72            // fp16 smem row stride (64 + 8 pad)
#define ASH_W  (BM*LDH)      // 4608 halfs / stage
#define BSH_W  (40*LDH)      // 2880 halfs / stage
#define DSMEM  (NSTG*(ASH_W+BSH_W)*2)   // 74880 bytes

// ---------------- persistent device state ----------------
__device__ __half gAh[25000000];               // fp16 copy of adj (50MB, fits L2)
__device__ __align__(16) float g_X0T[NF*TST];
__device__ __align__(16) float g_X1T[NF*TST];
__device__ __align__(16) float g_X2T[NF*TST];
__device__ __align__(16) float g_C0T[NF*TST];
__device__ __align__(16) float g_C1T[NF*TST];
__device__ __align__(16) float g_C2T[NF*TST];
__device__ __align__(16) __half g_X0h[NF*TSTH];
__device__ __align__(16) __half g_X1h[NF*TSTH];
__device__ __align__(16) __half g_C0h[NF*TSTH];
__device__ __align__(16) __half g_C1h[NF*TSTH];
__device__ float g_hT[NU*TST];
__device__ float g_uT[NU*TST];
__device__ unsigned g_cnt0[MT];                // split-K completion counters
__device__ unsigned g_cnt2[MT];

// ---------------- helpers ----------------
__device__ __forceinline__ void cp16z(void* dst, const void* src, int bytes) {
    unsigned s = (unsigned)__cvta_generic_to_shared(dst);
    asm volatile("cp.async.cg.shared.global [%0], [%1], 16, %2;\n"
                 :: "r"(s), "l"(src), "r"(bytes));
}
// A loads: evict_last so the 50MB fp16 adj pins in L2 across all 96 GEMMs
__device__ __forceinline__ void cp16pol(void* dst, const void* src, int bytes,
                                        unsigned long long pol) {
    unsigned s = (unsigned)__cvta_generic_to_shared(dst);
    asm volatile("cp.async.cg.shared.global.L2::cache_hint [%0], [%1], 16, %2, %3;\n"
                 :: "r"(s), "l"(src), "r"(bytes), "l"(pol));
}
__device__ __forceinline__ void mma_f16(float* c, unsigned a0, unsigned a1,
                                        unsigned a2, unsigned a3,
                                        unsigned b0, unsigned b1) {
    asm volatile("mma.sync.aligned.m16n8k16.row.col.f32.f16.f16.f32 "
                 "{%0,%1,%2,%3}, {%4,%5,%6,%7}, {%8,%9}, {%0,%1,%2,%3};"
                 : "+f"(c[0]), "+f"(c[1]), "+f"(c[2]), "+f"(c[3])
                 : "r"(a0), "r"(a1), "r"(a2), "r"(a3), "r"(b0), "r"(b1));
}
#define CP_COMMIT() asm volatile("cp.async.commit_group;" ::: "memory")
#define CP_WAIT3()  asm volatile("cp.async.wait_group 3;" ::: "memory")

// ============================================================================
// fp16 mma GEMM: YT(f,r) += sum_k A(r,k) * Xh(f,k)
// 64 rows/CTA (4 warps x 16 rows), N=40 (33 used), K-tiles of 64, split-K=5.
// 5-stage cp.async ring, depth-4 lookahead (exact R8 structure).
// sel 0/2: last split-K CTA per M-tile converts fp32 output -> fp16 shadow.
// ============================================================================
__global__ void __launch_bounds__(128, 3) gemm_mma(int sel)
{
    const __half* __restrict__ XH;
    float* __restrict__ YT;
    __half* __restrict__ DH = nullptr;
    unsigned* cnt = nullptr;
    switch (sel) {
        case 0:  XH = g_X0h; YT = g_X1T; DH = g_X1h; cnt = g_cnt0; break;
        case 1:  XH = g_X1h; YT = g_X2T; break;
        case 2:  XH = g_C0h; YT = g_C1T; DH = g_C1h; cnt = g_cnt2; break;
        default: XH = g_C1h; YT = g_C2T; break;
    }

    extern __shared__ __half smh[];
    __half* as = smh;                  // [5][64][72]
    __half* bs = smh + NSTG*ASH_W;     // [5][40][72]
    __shared__ int isLast;

    unsigned long long pol;
    asm("createpolicy.fractional.L2::evict_last.b64 %0, 1.0;" : "=l"(pol));

    const int t    = threadIdx.x;
    const int w    = t >> 5, lane = t & 31;
    const int r4   = lane >> 2, c4 = lane & 3;
    const int rt   = blockIdx.x % MT;
    const int ck   = blockIdx.x / MT;
    const int row0 = rt * BM;
    const int tS   = (KT * ck)       / SPLITK;
    const int tE   = (KT * (ck + 1)) / SPLITK;
    const int nt   = tE - tS;

    // zero B pad rows 33..39 in all stages (loader never writes them)
    for (int i = t; i < NSTG * 7 * BK; i += 128) {
        int s = i / (7 * BK), rem = i % (7 * BK);
        bs[s*BSH_W + (33 + rem / BK) * LDH + (rem % BK)] = __half(0.f);
    }

    // A loader: thread -> row (t>>1), half (t&1)*32 halfs, 4 x 16B chunks
    const int tr = t >> 1, th = t & 1;
    const int grow = row0 + tr;
    const __half* aRow = gAh + (long)(grow < Nn ? grow : Nn - 1) * Nn;

    auto load_tile = [&](int tile, int s) {
        const int k0 = tile * BK;
        __half* ad = as + s*ASH_W + tr*LDH + th*32;
        #pragma unroll
        for (int ch = 0; ch < 4; ++ch) {
            int gk = k0 + th*32 + ch*8;                     // 8 halfs = 16B
            int bytes = (grow < Nn && gk + 8 <= Nn) ? 16 : 0;  // zero-fill OOB
            cp16pol(ad + ch*8, aRow + (gk + 8 <= Nn ? gk : Nn - 8), bytes, pol);
        }
        __half* bd = bs + s*BSH_W;
        #pragma unroll
        for (int j = 0; j < 3; ++j) {
            int c = j * 128 + t;
            if (c < 264) {                                  // 33 rows x 8 chunks
                int row = c >> 3, ch = c & 7;
                cp16z(bd + row*LDH + ch*8, XH + (long)row*TSTH + k0 + ch*8, 16);
            }
        }
    };

    float acc[5][4];
    #pragma unroll
    for (int ct = 0; ct < 5; ++ct)
        #pragma unroll
        for (int i = 0; i < 4; ++i) acc[ct][i] = 0.f;

    #pragma unroll
    for (int p = 0; p < 4; ++p) {
        if (p < nt) load_tile(tS + p, p);
        CP_COMMIT();
    }

    for (int i = 0; i < nt; ++i) {
        CP_WAIT3();
        __syncthreads();
        if (i + 4 < nt) load_tile(tS + i + 4, (i + 4) % NSTG);
        CP_COMMIT();

        const int stage = i % NSTG;
        const __half* aB = as + stage*ASH_W + (w*16)*LDH;
        const __half* bB = bs + stage*BSH_W;
        #pragma unroll
        for (int ks = 0; ks < 4; ++ks) {
            const int kb = ks*16 + 2*c4;
            unsigned a0 = *(const unsigned*)(aB + (r4    )*LDH + kb    );
            unsigned a1 = *(const unsigned*)(aB + (r4 + 8)*LDH + kb    );
            unsigned a2 = *(const unsigned*)(aB + (r4    )*LDH + kb + 8);
            unsigned a3 = *(const unsigned*)(aB + (r4 + 8)*LDH + kb + 8);
            #pragma unroll
            for (int ct = 0; ct < 5; ++ct) {
                unsigned b0 = *(const unsigned*)(bB + (ct*8 + r4)*LDH + kb    );
                unsigned b1 = *(const unsigned*)(bB + (ct*8 + r4)*LDH + kb + 8);
                mma_f16(acc[ct], a0, a1, a2, a3, b0, b1);
            }
        }
    }

    const int rA = row0 + w*16 + r4;
    const int rB = rA + 8;
    #pragma unroll
    for (int ct = 0; ct < 5; ++ct) {
        const int col0 = ct*8 + 2*c4;
        const int col1 = col0 + 1;
        if (col0 < NF) {
            if (rA < Nn) atomicAdd(YT + (long)col0*TST + rA, acc[ct][0]);
            if (rB < Nn) atomicAdd(YT + (long)col0*TST + rB, acc[ct][2]);
        }
        if (col1 < NF) {
            if (rA < Nn) atomicAdd(YT + (long)col1*TST + rA, acc[ct][1]);
            if (rB < Nn) atomicAdd(YT + (long)col1*TST + rB, acc[ct][3]);
        }
    }

    // fused fp32 -> fp16 conversion by the last split-K CTA of this M-tile
    if (DH) {
        __threadfence();
        if (t == 0) isLast = (atomicAdd(&cnt[rt], 1u) == SPLITK - 1);
        __syncthreads();
        if (isLast) {
            __threadfence();
            for (int idx = t; idx < BM * NF; idx += 128) {
                int c = idx / BM, r = row0 + (idx % BM);
                if (r < Nn) DH[(long)c*TSTH + r] = __float2half_rn(YT[(long)c*TST + r]);
            }
            if (t == 0) cnt[rt] = 0;
        }
    }
}

// ============================================================================
// Prep / elementwise kernels
// ============================================================================
__global__ void conv_A(const float* __restrict__ A) {
    long i0 = (long)blockIdx.x * blockDim.x + threadIdx.x;
    long stride = (long)gridDim.x * blockDim.x;
    for (long i = i0; i < (long)Nn * Nn; i += stride) gAh[i] = __float2half_rn(A[i]);
}

__global__ void init_k() {
    int tid = blockIdx.x * blockDim.x + threadIdx.x;
    int nth = gridDim.x * blockDim.x;
    for (int j = tid; j < NF * TST; j += nth) {
        g_X0T[j] = 0.f; g_X1T[j] = 0.f; g_X2T[j] = 0.f;
        g_C0T[j] = 0.f; g_C1T[j] = 0.f; g_C2T[j] = 0.f;
    }
    for (int j = tid; j < NF * TSTH; j += nth) {
        g_X0h[j] = __half(0.f); g_X1h[j] = __half(0.f);
        g_C0h[j] = __half(0.f); g_C1h[j] = __half(0.f);
    }
    for (int j = tid; j < NU * TST; j += nth) { g_hT[j] = 0.f; g_uT[j] = 0.f; }
    for (int j = tid; j < MT; j += nth) { g_cnt0[j] = 0u; g_cnt2[j] = 0u; }
}

__global__ void build_enc(const float* __restrict__ inp, int tstep) {
    int tid = blockIdx.x * blockDim.x + threadIdx.x;
    int nth = gridDim.x * blockDim.x;
    for (int j = tid; j < NF * TST; j += nth) {
        int c = j / TST, n = j - c * TST;
        float v = 0.f;
        if (n < Nn) v = (c == 0) ? inp[n * TENC + tstep] : g_hT[(c - 1) * TST + n];
        g_X0T[j] = v;
        g_X0h[c * TSTH + n] = __float2half_rn(v);
        g_X1T[j] = 0.f; g_X2T[j] = 0.f;
    }
}

__global__ void build_dec0() {
    int tid = blockIdx.x * blockDim.x + threadIdx.x;
    int nth = gridDim.x * blockDim.x;
    for (int j = tid; j < NF * TST; j += nth) {
        int c = j / TST, n = j - c * TST;
        float v = 0.f;
        if (n < Nn && c > 0) v = g_hT[(c - 1) * TST + n];
        g_X0T[j] = v;
        g_X0h[c * TSTH + n] = __float2half_rn(v);
        g_X1T[j] = 0.f; g_X2T[j] = 0.f;
    }
}

__global__ void __launch_bounds__(256) gate_k(const float* __restrict__ W,
                                              const float* __restrict__ b) {
    __shared__ float sW[99 * 64];
    __shared__ float sx[99 * 32];
    const int t = threadIdx.x, lane = t & 31, w = t >> 5;
    const int rowb = blockIdx.x * 32;
    for (int j = t; j < 99 * 64; j += 256) sW[j] = W[j];
    for (int j = t; j < 99 * 32; j += 256) {
        int c = j >> 5, i = j & 31;
        const float* src = (c < 33) ? (g_X0T + c * TST)
                         : (c < 66) ? (g_X1T + (c - 33) * TST)
                                    : (g_X2T + (c - 66) * TST);
        sx[j] = src[rowb + i];
    }
    __syncthreads();

    float acc[8];
    #pragma unroll
    for (int cc = 0; cc < 8; ++cc) acc[cc] = b[8 * w + cc];
    for (int k = 0; k < 99; ++k) {
        float xv = sx[k * 32 + lane];
        const float4* wr = reinterpret_cast<const float4*>(sW + k * 64 + 8 * w);
        float4 w0 = wr[0], w1 = wr[1];
        acc[0] = fmaf(xv, w0.x, acc[0]); acc[1] = fmaf(xv, w0.y, acc[1]);
        acc[2] = fmaf(xv, w0.z, acc[2]); acc[3] = fmaf(xv, w0.w, acc[3]);
        acc[4] = fmaf(xv, w1.x, acc[4]); acc[5] = fmaf(xv, w1.y, acc[5]);
        acc[6] = fmaf(xv, w1.z, acc[6]); acc[7] = fmaf(xv, w1.w, acc[7]);
    }
    int row = rowb + lane;
    if (row < Nn) {
        #pragma unroll
        for (int cc = 0; cc < 8; ++cc) {
            int col = 8 * w + cc;
            float s = 1.f / (1.f + expf(-acc[cc]));
            if (col < 32) {
                float rh = s * g_hT[col * TST + row];
                g_C0T[(1 + col) * TST + row] = rh;
                g_C0h[(1 + col) * TSTH + row] = __float2half_rn(rh);
            } else {
                g_uT[(col - 32) * TST + row] = s;
            }
        }
        if (w == 0) {
            g_C0T[row] = g_X0T[row];
            g_C0h[row] = g_X0h[row];
        }
    }
    int tid = blockIdx.x * 256 + t, nth = gridDim.x * 256;
    for (int j = tid; j < NF * TST; j += nth) { g_C1T[j] = 0.f; g_C2T[j] = 0.f; }
}

__global__ void __launch_bounds__(256) cand_k(const float* __restrict__ W,
                                              const float* __restrict__ b) {
    __shared__ float sW[99 * 32];
    __shared__ float sx[99 * 32];
    const int t = threadIdx.x, lane = t & 31, w = t >> 5;
    const int rowb = blockIdx.x * 32;
    for (int j = t; j < 99 * 32; j += 256) sW[j] = W[j];
    for (int j = t; j < 99 * 32; j += 256) {
        int c = j >> 5, i = j & 31;
        const float* src = (c < 33) ? (g_C0T + c * TST)
                         : (c < 66) ? (g_C1T + (c - 33) * TST)
                                    : (g_C2T + (c - 66) * TST);
        sx[j] = src[rowb + i];
    }
    __syncthreads();

    float acc[4];
    #pragma unroll
    for (int cc = 0; cc < 4; ++cc) acc[cc] = b[4 * w + cc];
    for (int k = 0; k < 99; ++k) {
        float xv = sx[k * 32 + lane];
        float4 wv = *reinterpret_cast<const float4*>(sW + k * 32 + 4 * w);
        acc[0] = fmaf(xv, wv.x, acc[0]); acc[1] = fmaf(xv, wv.y, acc[1]);
        acc[2] = fmaf(xv, wv.z, acc[2]); acc[3] = fmaf(xv, wv.w, acc[3]);
    }
    int row = rowb + lane;
    if (row < Nn) {
        #pragma unroll
        for (int cc = 0; cc < 4; ++cc) {
            int col = 4 * w + cc;
            float c = tanhf(acc[cc]);
            float u = g_uT[col * TST + row];
            float h = g_hT[col * TST + row];
            g_hT[col * TST + row] = u * h + (1.f - u) * c;
        }
    }
}

__global__ void __launch_bounds__(256) dec_post(const float* __restrict__ Wp,
                                                const float* __restrict__ bp,
                                                float* __restrict__ out, int tstep) {
    int tid = blockIdx.x * 256 + threadIdx.x;
    int nth = gridDim.x * 256;
    for (int row = tid; row < Nn; row += nth) {
        float acc = bp[0];
        #pragma unroll
        for (int c = 0; c < 32; ++c) acc = fmaf(g_hT[c * TST + row], Wp[c], acc);
        out[row * TDEC + tstep] = acc;
        g_X0T[row] = acc;
        g_X0h[row] = __float2half_rn(acc);
    }
    for (int j = tid; j < NU * TST; j += nth) {
        int c = j / TST, n = j - c * TST;
        float h = g_hT[j];
        g_X0T[TST + j] = h;
        g_X0h[(1 + c) * TSTH + n] = __float2half_rn(h);
    }
    for (int j = tid; j < NF * TST; j += nth) { g_X1T[j] = 0.f; g_X2T[j] = 0.f; }
}

// ============================================================================
// Host launch sequence
// ============================================================================
extern "C" void kernel_launch(void* const* d_in, const int* in_sizes, int n_in,
                              void* d_out, int out_size) {
    const float* inputs = (const float*)d_in[0];
    const float* adj    = (const float*)d_in[2];
    const float* enc_Wg = (const float*)d_in[3];
    const float* enc_bg = (const float*)d_in[4];
    const float* enc_Wc = (const float*)d_in[5];
    const float* enc_bc = (const float*)d_in[6];
    const float* dec_Wg = (const float*)d_in[7];
    const float* dec_bg = (const float*)d_in[8];
    const float* dec_Wc = (const float*)d_in[9];
    const float* dec_bc = (const float*)d_in[10];
    const float* dec_Wp = (const float*)d_in[11];
    const float* dec_bp = (const float*)d_in[12];
    float* out = (float*)d_out;

    cudaFuncSetAttribute(gemm_mma, cudaFuncAttributeMaxDynamicSharedMemorySize, DSMEM);
    cudaFuncSetAttribute(gemm_mma, cudaFuncAttributePreferredSharedMemoryCarveout, 100);

    conv_A<<<1024, 256>>>(adj);
    init_k<<<256, 256>>>();

    for (int t = 0; t < TENC; ++t) {
        build_enc<<<256, 256>>>(inputs, t);
        gemm_mma<<<GGRID, 128, DSMEM>>>(0);
        gemm_mma<<<GGRID, 128, DSMEM>>>(1);
        gate_k<<<157, 256>>>(enc_Wg, enc_bg);
        gemm_mma<<<GGRID, 128, DSMEM>>>(2);
        gemm_mma<<<GGRID, 128, DSMEM>>>(3);
        cand_k<<<157, 256>>>(enc_Wc, enc_bc);
    }

    build_dec0<<<256, 256>>>();
    for (int t = 0; t < TDEC; ++t) {
        gemm_mma<<<GGRID, 128, DSMEM>>>(0);
        gemm_mma<<<GGRID, 128, DSMEM>>>(1);
        gate_k<<<157, 256>>>(dec_Wg, dec_bg);
        gemm_mma<<<GGRID, 128, DSMEM>>>(2);
        gemm_mma<<<GGRID, 128, DSMEM>>>(3);
        cand_k<<<157, 256>>>(dec_Wc, dec_bc);
        dec_post<<<157, 256>>>(dec_Wp, dec_bp, out, t);
    }
}

// round 11
// speedup vs baseline: 1.6426x; 1.4483x over previous
#include <cuda_runtime.h>
#include <cuda_fp16.h>
#include <cstdint>

#define Nn     5000
#define TST    5024          // fp32 buffer node stride
#define NF     33
#define NU     32
#define TENC   12
#define TDEC   12
#define BM     64
#define MT     79            // M tiles of 64
#define SPLITK 5
#define GGRID  (MT*SPLITK)   // 395
#define KT     79            // K tiles of 64
#define BK     64
#define NSTG   5
#define ATILE_H 4096         // halfs per A tile (64x64)
#define BTILE_H 2560         // halfs per B tile (40x64)
#define STG_B   ((ATILE_H+BTILE_H)*2)   // 13312 bytes per stage
#define DSMEM   (NSTG*STG_B)            // 66560 bytes
#define TXB     13312

// ---------------- persistent device state ----------------
__device__ __half gAt[(long)MT*KT*ATILE_H];    // tiled+swizzled fp16 adj (51MB)
__device__ __align__(16) float g_X0T[NF*TST];
__device__ __align__(16) float g_X1T[NF*TST];
__device__ __align__(16) float g_X2T[NF*TST];
__device__ __align__(16) float g_C0T[NF*TST];
__device__ __align__(16) float g_C1T[NF*TST];
__device__ __align__(16) float g_C2T[NF*TST];
// fp16 shadows in TILE layout: [kt][40 rows][64 halfs], swizzled, pads zero
__device__ __align__(16) __half g_X0h[KT*BTILE_H];
__device__ __align__(16) __half g_X1h[KT*BTILE_H];
__device__ __align__(16) __half g_C0h[KT*BTILE_H];
__device__ __align__(16) __half g_C1h[KT*BTILE_H];
__device__ float g_hT[NU*TST];
__device__ float g_uT[NU*TST];
__device__ unsigned g_cnt0[MT];
__device__ unsigned g_cnt2[MT];

// ---------------- helpers ----------------
__device__ __forceinline__ unsigned su32(const void* p) {
    return (unsigned)__cvta_generic_to_shared(p);
}
// byte offset of (row, kh) within a swizzled tile (kh < 64)
__device__ __forceinline__ int swb(int row, int kh) {
    return row * 128 + ((kh * 2) ^ ((row & 7) << 4));
}
// half-index of (feature c, node n) in a tile-layout X shadow
__device__ __forceinline__ int xh_idx(int c, int n) {
    int kt = n >> 6, kn = n & 63;
    return kt * BTILE_H + (swb(c, kn) >> 1);
}
__device__ __forceinline__ void bulk_cp(unsigned dst, const void* src,
                                        unsigned bytes, unsigned mbar) {
    asm volatile("cp.async.bulk.shared::cluster.global.mbarrier::complete_tx::bytes "
                 "[%0], [%1], %2, [%3];"
                 :: "r"(dst), "l"(src), "r"(bytes), "r"(mbar) : "memory");
}
__device__ __forceinline__ void mbar_init(unsigned a, unsigned c) {
    asm volatile("mbarrier.init.shared.b64 [%0], %1;" :: "r"(a), "r"(c) : "memory");
}
__device__ __forceinline__ void mbar_expect(unsigned a, unsigned tx) {
    asm volatile("mbarrier.arrive.expect_tx.shared.b64 _, [%0], %1;"
                 :: "r"(a), "r"(tx) : "memory");
}
__device__ __forceinline__ void mbar_wait(unsigned a, unsigned ph) {
    asm volatile("{\n\t.reg .pred P;\n\t"
                 "W%=:\n\tmbarrier.try_wait.parity.acquire.cta.shared::cta.b64 P, [%0], %1, 0x989680;\n\t"
                 "@!P bra W%=;\n\t}" :: "r"(a), "r"(ph) : "memory");
}
__device__ __forceinline__ void mma_f16(float* c, unsigned a0, unsigned a1,
                                        unsigned a2, unsigned a3,
                                        unsigned b0, unsigned b1) {
    asm volatile("mma.sync.aligned.m16n8k16.row.col.f32.f16.f16.f32 "
                 "{%0,%1,%2,%3}, {%4,%5,%6,%7}, {%8,%9}, {%0,%1,%2,%3};"
                 : "+f"(c[0]), "+f"(c[1]), "+f"(c[2]), "+f"(c[3])
                 : "r"(a0), "r"(a1), "r"(a2), "r"(a3), "r"(b0), "r"(b1));
}

// ============================================================================
// fp16 mma GEMM: YT(f,r) += sum_k A(r,k) * Xh(f,k)
// One 8KB A-bulk + one 5KB B-bulk per k-tile; 5-stage mbarrier ring, depth 4.
// sel 0/2: last split-K CTA per M-tile converts fp32 output -> fp16 tile shadow.
// ============================================================================
__global__ void __launch_bounds__(128, 3) gemm_mma(int sel)
{
    const __half* __restrict__ XH;
    float* __restrict__ YT;
    __half* __restrict__ DH = nullptr;
    unsigned* cnt = nullptr;
    switch (sel) {
        case 0:  XH = g_X0h; YT = g_X1T; DH = g_X1h; cnt = g_cnt0; break;
        case 1:  XH = g_X1h; YT = g_X2T; break;
        case 2:  XH = g_C0h; YT = g_C1T; DH = g_C1h; cnt = g_cnt2; break;
        default: XH = g_C1h; YT = g_C2T; break;
    }

    extern __shared__ char smc[];      // [5][A 8192B | B 5120B]
    __shared__ __align__(8) unsigned long long mbar[NSTG];
    __shared__ int isLast;

    const int t    = threadIdx.x;
    const int w    = t >> 5, lane = t & 31;
    const int r4   = lane >> 2, c4 = lane & 3;
    const int rt   = blockIdx.x % MT;
    const int ck   = blockIdx.x / MT;
    const int row0 = rt * BM;
    const int tS   = (KT * ck)       / SPLITK;
    const int tE   = (KT * (ck + 1)) / SPLITK;
    const int nt   = tE - tS;

    if (t == 0) {
        #pragma unroll
        for (int s = 0; s < NSTG; ++s) mbar_init(su32(&mbar[s]), 1);
    }
    asm volatile("fence.proxy.async.shared::cta;" ::: "memory");
    __syncthreads();

    auto load_tile = [&](int tile, int s) {
        if (t == 0) {
            unsigned mb = su32(&mbar[s]);
            mbar_expect(mb, TXB);
            bulk_cp(su32(smc + s*STG_B), gAt + ((long)(rt*KT + tile))*ATILE_H, 8192, mb);
            bulk_cp(su32(smc + s*STG_B + 8192), XH + (long)tile*BTILE_H, 5120, mb);
        }
    };

    float acc[5][4];
    #pragma unroll
    for (int ct = 0; ct < 5; ++ct)
        #pragma unroll
        for (int i = 0; i < 4; ++i) acc[ct][i] = 0.f;

    #pragma unroll
    for (int p = 0; p < 4; ++p)
        if (p < nt) load_tile(tS + p, p);

    const int w16 = w * 16;
    const int xm  = (r4 & 7) << 4;     // swizzle XOR for this lane's rows

    for (int i = 0; i < nt; ++i) {
        __syncthreads();               // all warps done with iter i-1 compute
        if (i + 4 < nt) load_tile(tS + i + 4, (i + 4) % NSTG);
        mbar_wait(su32(&mbar[i % NSTG]), (unsigned)(i / NSTG) & 1);

        const char* aC = smc + (i % NSTG) * STG_B;
        const char* bC = aC + 8192;
        #pragma unroll
        for (int ks = 0; ks < 4; ++ks) {
            const int kby = ((ks*16 + 2*c4) * 2) ^ xm;     // swizzled byte off of kb
            const int kby8 = ((ks*16 + 2*c4 + 8) * 2) ^ xm;
            unsigned a0 = *(const unsigned*)(aC + (w16 + r4    )*128 + kby );
            unsigned a1 = *(const unsigned*)(aC + (w16 + r4 + 8)*128 + kby );
            unsigned a2 = *(const unsigned*)(aC + (w16 + r4    )*128 + kby8);
            unsigned a3 = *(const unsigned*)(aC + (w16 + r4 + 8)*128 + kby8);
            #pragma unroll
            for (int ct = 0; ct < 5; ++ct) {
                unsigned b0 = *(const unsigned*)(bC + (ct*8 + r4)*128 + kby );
                unsigned b1 = *(const unsigned*)(bC + (ct*8 + r4)*128 + kby8);
                mma_f16(acc[ct], a0, a1, a2, a3, b0, b1);
            }
        }
    }

    const int rA = row0 + w16 + r4;
    const int rB = rA + 8;
    #pragma unroll
    for (int ct = 0; ct < 5; ++ct) {
        const int col0 = ct*8 + 2*c4;
        const int col1 = col0 + 1;
        if (col0 < NF) {
            if (rA < Nn) atomicAdd(YT + (long)col0*TST + rA, acc[ct][0]);
            if (rB < Nn) atomicAdd(YT + (long)col0*TST + rB, acc[ct][2]);
        }
        if (col1 < NF) {
            if (rA < Nn) atomicAdd(YT + (long)col1*TST + rA, acc[ct][1]);
            if (rB < Nn) atomicAdd(YT + (long)col1*TST + rB, acc[ct][3]);
        }
    }

    // fused fp32 -> fp16 tile-shadow conversion by the last split-K CTA
    if (DH) {
        __threadfence();
        if (t == 0) isLast = (atomicAdd(&cnt[rt], 1u) == SPLITK - 1);
        __syncthreads();
        if (isLast) {
            __threadfence();
            for (int idx = t; idx < BM * NF; idx += 128) {
                int c = idx >> 6, kn = idx & 63;
                int r = row0 + kn;
                if (r < Nn)
                    DH[xh_idx(c, r)] = __float2half_rn(YT[(long)c*TST + r]);
            }
            if (t == 0) cnt[rt] = 0;
        }
    }
}

// ============================================================================
// Prep: adj fp32 -> tiled, swizzled fp16 (zero-padded). Warp = 2 tile rows.
// ============================================================================
__global__ void conv_A(const float* __restrict__ A) {
    const int lane = threadIdx.x & 31;
    const int rh = lane >> 4;             // 0..1 row within pair
    const int l16 = lane & 15;            // 4 cols each
    long gw0 = (long)blockIdx.x * 8 + (threadIdx.x >> 5);
    const long total = (long)MT * KT * 32;    // row-pairs
    for (long gw = gw0; gw < total; gw += (long)gridDim.x * 8) {
        int rp = (int)(gw & 31);
        long t2 = gw >> 5;
        int kt = (int)(t2 % KT);
        int mt = (int)(t2 / KT);
        int r = rp * 2 + rh;
        int grow = mt * 64 + r;
        int gk = kt * 64 + l16 * 4;
        float v0 = 0.f, v1 = 0.f, v2 = 0.f, v3 = 0.f;
        if (grow < Nn) {
            const float* src = A + (long)grow * Nn + gk;
            if (gk + 3 < Nn) {
                float4 vv = *(const float4*)src;
                v0 = vv.x; v1 = vv.y; v2 = vv.z; v3 = vv.w;
            } else {
                if (gk     < Nn) v0 = src[0];
                if (gk + 1 < Nn) v1 = src[1];
                if (gk + 2 < Nn) v2 = src[2];
                if (gk + 3 < Nn) v3 = src[3];
            }
        }
        __half2 h01 = __floats2half2_rn(v0, v1);
        __half2 h23 = __floats2half2_rn(v2, v3);
        int off = swb(r, l16 * 4);        // 8B aligned after swizzle
        char* dst = (char*)gAt + ((long)(mt*KT + kt))*8192 + off;
        ((unsigned*)dst)[0] = *(unsigned*)&h01;
        ((unsigned*)dst)[1] = *(unsigned*)&h23;
    }
}

// ============================================================================
// Elementwise kernels
// ============================================================================
__global__ void init_k() {
    int tid = blockIdx.x * blockDim.x + threadIdx.x;
    int nth = gridDim.x * blockDim.x;
    for (int j = tid; j < NF * TST; j += nth) {
        g_X0T[j] = 0.f; g_X1T[j] = 0.f; g_X2T[j] = 0.f;
        g_C0T[j] = 0.f; g_C1T[j] = 0.f; g_C2T[j] = 0.f;
    }
    for (int j = tid; j < KT * BTILE_H; j += nth) {
        g_X0h[j] = __half(0.f); g_X1h[j] = __half(0.f);
        g_C0h[j] = __half(0.f); g_C1h[j] = __half(0.f);
    }
    for (int j = tid; j < NU * TST; j += nth) { g_hT[j] = 0.f; g_uT[j] = 0.f; }
    for (int j = tid; j < MT; j += nth) { g_cnt0[j] = 0u; g_cnt2[j] = 0u; }
}

__global__ void build_enc(const float* __restrict__ inp, int tstep) {
    int tid = blockIdx.x * blockDim.x + threadIdx.x;
    int nth = gridDim.x * blockDim.x;
    for (int j = tid; j < NF * TST; j += nth) {
        int c = j / TST, n = j - c * TST;
        float v = 0.f;
        if (n < Nn) {
            v = (c == 0) ? inp[n * TENC + tstep] : g_hT[(c - 1) * TST + n];
            g_X0h[xh_idx(c, n)] = __float2half_rn(v);
        }
        g_X0T[j] = v;
        g_X1T[j] = 0.f; g_X2T[j] = 0.f;
    }
}

__global__ void build_dec0() {
    int tid = blockIdx.x * blockDim.x + threadIdx.x;
    int nth = gridDim.x * blockDim.x;
    for (int j = tid; j < NF * TST; j += nth) {
        int c = j / TST, n = j - c * TST;
        float v = 0.f;
        if (n < Nn) {
            if (c > 0) v = g_hT[(c - 1) * TST + n];
            g_X0h[xh_idx(c, n)] = __float2half_rn(v);
        }
        g_X0T[j] = v;
        g_X1T[j] = 0.f; g_X2T[j] = 0.f;
    }
}

__global__ void __launch_bounds__(256) gate_k(const float* __restrict__ W,
                                              const float* __restrict__ b) {
    __shared__ float sW[99 * 64];
    __shared__ float sx[99 * 32];
    const int t = threadIdx.x, lane = t & 31, w = t >> 5;
    const int rowb = blockIdx.x * 32;
    for (int j = t; j < 99 * 64; j += 256) sW[j] = W[j];
    for (int j = t; j < 99 * 32; j += 256) {
        int c = j >> 5, i = j & 31;
        const float* src = (c < 33) ? (g_X0T + c * TST)
                         : (c < 66) ? (g_X1T + (c - 33) * TST)
                                    : (g_X2T + (c - 66) * TST);
        sx[j] = src[rowb + i];
    }
    __syncthreads();

    float acc[8];
    #pragma unroll
    for (int cc = 0; cc < 8; ++cc) acc[cc] = b[8 * w + cc];
    for (int k = 0; k < 99; ++k) {
        float xv = sx[k * 32 + lane];
        const float4* wr = reinterpret_cast<const float4*>(sW + k * 64 + 8 * w);
        float4 w0 = wr[0], w1 = wr[1];
        acc[0] = fmaf(xv, w0.x, acc[0]); acc[1] = fmaf(xv, w0.y, acc[1]);
        acc[2] = fmaf(xv, w0.z, acc[2]); acc[3] = fmaf(xv, w0.w, acc[3]);
        acc[4] = fmaf(xv, w1.x, acc[4]); acc[5] = fmaf(xv, w1.y, acc[5]);
        acc[6] = fmaf(xv, w1.z, acc[6]); acc[7] = fmaf(xv, w1.w, acc[7]);
    }
    int row = rowb + lane;
    if (row < Nn) {
        #pragma unroll
        for (int cc = 0; cc < 8; ++cc) {
            int col = 8 * w + cc;
            float s = 1.f / (1.f + expf(-acc[cc]));
            if (col < 32) {
                float rh = s * g_hT[col * TST + row];
                g_C0T[(1 + col) * TST + row] = rh;
                g_C0h[xh_idx(1 + col, row)] = __float2half_rn(rh);
            } else {
                g_uT[(col - 32) * TST + row] = s;
            }
        }
        if (w == 0) {
            float x0 = g_X0T[row];
            g_C0T[row] = x0;
            g_C0h[xh_idx(0, row)] = __float2half_rn(x0);
        }
    }
    int tid = blockIdx.x * 256 + t, nth = gridDim.x * 256;
    for (int j = tid; j < NF * TST; j += nth) { g_C1T[j] = 0.f; g_C2T[j] = 0.f; }
}

__global__ void __launch_bounds__(256) cand_k(const float* __restrict__ W,
                                              const float* __restrict__ b) {
    __shared__ float sW[99 * 32];
    __shared__ float sx[99 * 32];
    const int t = threadIdx.x, lane = t & 31, w = t >> 5;
    const int rowb = blockIdx.x * 32;
    for (int j = t; j < 99 * 32; j += 256) sW[j] = W[j];
    for (int j = t; j < 99 * 32; j += 256) {
        int c = j >> 5, i = j & 31;
        const float* src = (c < 33) ? (g_C0T + c * TST)
                         : (c < 66) ? (g_C1T + (c - 33) * TST)
                                    : (g_C2T + (c - 66) * TST);
        sx[j] = src[rowb + i];
    }
    __syncthreads();

    float acc[4];
    #pragma unroll
    for (int cc = 0; cc < 4; ++cc) acc[cc] = b[4 * w + cc];
    for (int k = 0; k < 99; ++k) {
        float xv = sx[k * 32 + lane];
        float4 wv = *reinterpret_cast<const float4*>(sW + k * 32 + 4 * w);
        acc[0] = fmaf(xv, wv.x, acc[0]); acc[1] = fmaf(xv, wv.y, acc[1]);
        acc[2] = fmaf(xv, wv.z, acc[2]); acc[3] = fmaf(xv, wv.w, acc[3]);
    }
    int row = rowb + lane;
    if (row < Nn) {
        #pragma unroll
        for (int cc = 0; cc < 4; ++cc) {
            int col = 4 * w + cc;
            float c = tanhf(acc[cc]);
            float u = g_uT[col * TST + row];
            float h = g_hT[col * TST + row];
            g_hT[col * TST + row] = u * h + (1.f - u) * c;
        }
    }
}

__global__ void __launch_bounds__(256) dec_post(const float* __restrict__ Wp,
                                                const float* __restrict__ bp,
                                                float* __restrict__ out, int tstep) {
    int tid = blockIdx.x * 256 + threadIdx.x;
    int nth = gridDim.x * 256;
    for (int row = tid; row < Nn; row += nth) {
        float acc = bp[0];
        #pragma unroll
        for (int c = 0; c < 32; ++c) acc = fmaf(g_hT[c * TST + row], Wp[c], acc);
        out[row * TDEC + tstep] = acc;
        g_X0T[row] = acc;
        g_X0h[xh_idx(0, row)] = __float2half_rn(acc);
    }
    for (int j = tid; j < NU * TST; j += nth) {
        int c = j / TST, n = j - c * TST;
        float h = g_hT[j];
        g_X0T[TST + j] = h;
        if (n < Nn) g_X0h[xh_idx(1 + c, n)] = __float2half_rn(h);
    }
    for (int j = tid; j < NF * TST; j += nth) { g_X1T[j] = 0.f; g_X2T[j] = 0.f; }
}

// ============================================================================
// Host launch sequence
// ============================================================================
extern "C" void kernel_launch(void* const* d_in, const int* in_sizes, int n_in,
                              void* d_out, int out_size) {
    const float* inputs = (const float*)d_in[0];
    const float* adj    = (const float*)d_in[2];
    const float* enc_Wg = (const float*)d_in[3];
    const float* enc_bg = (const float*)d_in[4];
    const float* enc_Wc = (const float*)d_in[5];
    const float* enc_bc = (const float*)d_in[6];
    const float* dec_Wg = (const float*)d_in[7];
    const float* dec_bg = (const float*)d_in[8];
    const float* dec_Wc = (const float*)d_in[9];
    const float* dec_bc = (const float*)d_in[10];
    const float* dec_Wp = (const float*)d_in[11];
    const float* dec_bp = (const float*)d_in[12];
    float* out = (float*)d_out;

    cudaFuncSetAttribute(gemm_mma, cudaFuncAttributeMaxDynamicSharedMemorySize, DSMEM);
    cudaFuncSetAttribute(gemm_mma, cudaFuncAttributePreferredSharedMemoryCarveout, 100);

    conv_A<<<4096, 256>>>(adj);
    init_k<<<256, 256>>>();

    for (int t = 0; t < TENC; ++t) {
        build_enc<<<256, 256>>>(inputs, t);
        gemm_mma<<<GGRID, 128, DSMEM>>>(0);
        gemm_mma<<<GGRID, 128, DSMEM>>>(1);
        gate_k<<<157, 256>>>(enc_Wg, enc_bg);
        gemm_mma<<<GGRID, 128, DSMEM>>>(2);
        gemm_mma<<<GGRID, 128, DSMEM>>>(3);
        cand_k<<<157, 256>>>(enc_Wc, enc_bc);
    }

    build_dec0<<<256, 256>>>();
    for (int t = 0; t < TDEC; ++t) {
        gemm_mma<<<GGRID, 128, DSMEM>>>(0);
        gemm_mma<<<GGRID, 128, DSMEM>>>(1);
        gate_k<<<157, 256>>>(dec_Wg, dec_bg);
        gemm_mma<<<GGRID, 128, DSMEM>>>(2);
        gemm_mma<<<GGRID, 128, DSMEM>>>(3);
        cand_k<<<157, 256>>>(dec_Wc, dec_bc);
        dec_post<<<157, 256>>>(dec_Wp, dec_bp, out, t);
    }
}